// round 2
// baseline (speedup 1.0000x reference)
#include <cuda_runtime.h>

#define N_NODES 50000
#define N_EDGES 1600000
#define E_TOT   (N_EDGES + N_NODES)
#define HID 64

// ---------------- scratch (static __device__: no allocation allowed) ----------------
__device__ int   g_is64;                // 1 if edge_index is int64, 0 if int32
__device__ int   g_deg[N_NODES];
__device__ float g_dis[N_NODES];
__device__ int   g_offs[N_NODES + 1];
__device__ int   g_cursor[N_NODES];
__device__ int   g_csr[E_TOT];
__device__ float g_ts[N_NODES * HID];   // dis-scaled transformed features (both layers)
__device__ float g_h [N_NODES * HID];   // layer-1 hidden output

// Dtype-dispatching edge-index load. ei is the base of edge_index [2, N_EDGES].
__device__ __forceinline__ int load_ei(const void* ei, long long flat_idx, int is64) {
    if (is64) return (int)((const long long*)ei)[flat_idx];
    return ((const int*)ei)[flat_idx];
}

// ---------------- dtype detection ----------------
// If int64: high word of each entry is 0 (indices in [0, 50000)). If int32:
// "high words" are other random indices; 64 of them all zero is impossible.
__global__ void k_detect(const int* __restrict__ ei_words) {
    int allzero = 1;
    for (int k = 0; k < 64; k++)
        if (ei_words[2 * k + 1] != 0) { allzero = 0; break; }
    g_is64 = allzero;
}

// ---------------- CSR build ----------------
__global__ void k_init() {
    int i = blockIdx.x * blockDim.x + threadIdx.x;
    if (i < N_NODES) g_deg[i] = 1;            // self-loop
}

__global__ void k_hist(const void* __restrict__ ei) {
    int e = blockIdx.x * blockDim.x + threadIdx.x;
    if (e < N_EDGES) {
        int d = load_ei(ei, (long long)N_EDGES + e, g_is64);
        atomicAdd(&g_deg[d], 1);
    }
}

// Single-block scan over 50K degrees: per-thread serial chunk + Hillis-Steele over 1024 partials.
// Also emits dis = rsqrt(deg), cursor = offs+1, and the self-loop CSR entry.
__global__ void k_scan() {
    __shared__ int s[1024];
    const int C = 49;                          // 1024*49 = 50176 >= 50000
    int t = threadIdx.x;
    int base = t * C;
    int local = 0;
    for (int j = 0; j < C; j++) { int i = base + j; if (i < N_NODES) local += g_deg[i]; }
    s[t] = local;
    __syncthreads();
    for (int off = 1; off < 1024; off <<= 1) {
        int v = (t >= off) ? s[t - off] : 0;
        __syncthreads();
        s[t] += v;
        __syncthreads();
    }
    int run = (t == 0) ? 0 : s[t - 1];
    for (int j = 0; j < C; j++) {
        int i = base + j;
        if (i < N_NODES) {
            int d = g_deg[i];
            g_offs[i]   = run;
            g_dis[i]    = rsqrtf((float)d);    // deg >= 1 always (self-loop)
            g_cursor[i] = run + 1;
            g_csr[run]  = i;                   // self-loop entry first
            run += d;
        } else if (i == N_NODES) {
            g_offs[N_NODES] = run;
        }
    }
}

__global__ void k_scatter(const void* __restrict__ ei) {
    int e = blockIdx.x * blockDim.x + threadIdx.x;
    if (e < N_EDGES) {
        int is64 = g_is64;
        int d = load_ei(ei, (long long)N_EDGES + e, is64);
        int s = load_ei(ei, e, is64);
        int pos = atomicAdd(&g_cursor[d], 1);
        g_csr[pos] = s;
    }
}

// ---------------- transform: OUT[i] = dis[i] * (X[i] @ W)  (64x64 weight) ----------------
// Block: 256 threads = 16x16, 4x4 register blocking on a 64-row x 64-col tile.
template <bool USE_H>
__global__ void __launch_bounds__(256) k_transform(const float* __restrict__ Xext,
                                                   const float* __restrict__ W) {
    __shared__ float4 ws4[64 * 16];
    __shared__ float  xs [64 * 64];
    const float* X = USE_H ? g_h : Xext;
    int tid  = threadIdx.x;
    int row0 = blockIdx.x * 64;

    for (int i = tid; i < 64 * 16; i += 256) ws4[i] = ((const float4*)W)[i];
    for (int i = tid; i < 64 * 16; i += 256) {
        int r = i >> 4, c4 = i & 15;
        int row = row0 + r;
        float4 v = make_float4(0.f, 0.f, 0.f, 0.f);
        if (row < N_NODES) v = ((const float4*)X)[row * 16 + c4];
        ((float4*)xs)[r * 16 + c4] = v;
    }
    __syncthreads();

    int tc = tid & 15, tr = tid >> 4;
    float acc[4][4];
#pragma unroll
    for (int a = 0; a < 4; a++)
#pragma unroll
        for (int b = 0; b < 4; b++) acc[a][b] = 0.f;

#pragma unroll 4
    for (int k = 0; k < 64; k++) {
        float4 wv = ws4[k * 16 + tc];
        float x0 = xs[(4 * tr + 0) * 64 + k];
        float x1 = xs[(4 * tr + 1) * 64 + k];
        float x2 = xs[(4 * tr + 2) * 64 + k];
        float x3 = xs[(4 * tr + 3) * 64 + k];
        acc[0][0] = fmaf(x0, wv.x, acc[0][0]); acc[0][1] = fmaf(x0, wv.y, acc[0][1]);
        acc[0][2] = fmaf(x0, wv.z, acc[0][2]); acc[0][3] = fmaf(x0, wv.w, acc[0][3]);
        acc[1][0] = fmaf(x1, wv.x, acc[1][0]); acc[1][1] = fmaf(x1, wv.y, acc[1][1]);
        acc[1][2] = fmaf(x1, wv.z, acc[1][2]); acc[1][3] = fmaf(x1, wv.w, acc[1][3]);
        acc[2][0] = fmaf(x2, wv.x, acc[2][0]); acc[2][1] = fmaf(x2, wv.y, acc[2][1]);
        acc[2][2] = fmaf(x2, wv.z, acc[2][2]); acc[2][3] = fmaf(x2, wv.w, acc[2][3]);
        acc[3][0] = fmaf(x3, wv.x, acc[3][0]); acc[3][1] = fmaf(x3, wv.y, acc[3][1]);
        acc[3][2] = fmaf(x3, wv.z, acc[3][2]); acc[3][3] = fmaf(x3, wv.w, acc[3][3]);
    }

#pragma unroll
    for (int jr = 0; jr < 4; jr++) {
        int row = row0 + 4 * tr + jr;
        if (row < N_NODES) {
            float sc = g_dis[row];
            float4 o = make_float4(acc[jr][0] * sc, acc[jr][1] * sc,
                                   acc[jr][2] * sc, acc[jr][3] * sc);
            ((float4*)g_ts)[row * 16 + tc] = o;
        }
    }
}

// ---------------- aggregate: one warp per node, CSR gather-sum, no atomics ----------------
// h[d] = relu(dis[d] * sum_{s in N(d)} ts[s] + b)
// FUSE_FC: instead of storing h, compute out = h @ Wfc + bfc (64 -> 10) via warp reduction.
template <bool FUSE_FC>
__global__ void __launch_bounds__(256) k_agg(const float* __restrict__ bias,
                                             const float* __restrict__ WFC,
                                             const float* __restrict__ BFC,
                                             float* __restrict__ OUT) {
    __shared__ float wfc_s[64 * 10];
    __shared__ float bfc_s[10];
    if (FUSE_FC) {
        for (int i = threadIdx.x; i < 640; i += blockDim.x) wfc_s[i] = WFC[i];
        if (threadIdx.x < 10) bfc_s[threadIdx.x] = BFC[threadIdx.x];
        __syncthreads();
    }
    int warp = (blockIdx.x * blockDim.x + threadIdx.x) >> 5;
    int lane = threadIdx.x & 31;
    if (warp >= N_NODES) return;

    int beg = g_offs[warp], end = g_offs[warp + 1];
    float a0 = 0.f, a1 = 0.f;
    int j = beg;
    for (; j + 4 <= end; j += 4) {
        int s0 = g_csr[j + 0], s1 = g_csr[j + 1];
        int s2 = g_csr[j + 2], s3 = g_csr[j + 3];
        const float* p0 = g_ts + s0 * HID;
        const float* p1 = g_ts + s1 * HID;
        const float* p2 = g_ts + s2 * HID;
        const float* p3 = g_ts + s3 * HID;
        float v00 = p0[lane], v01 = p0[lane + 32];
        float v10 = p1[lane], v11 = p1[lane + 32];
        float v20 = p2[lane], v21 = p2[lane + 32];
        float v30 = p3[lane], v31 = p3[lane + 32];
        a0 += (v00 + v10) + (v20 + v30);
        a1 += (v01 + v11) + (v21 + v31);
    }
    for (; j < end; j++) {
        int s0 = g_csr[j];
        a0 += g_ts[s0 * HID + lane];
        a1 += g_ts[s0 * HID + 32 + lane];
    }
    float d  = g_dis[warp];
    float h0 = fmaxf(fmaf(d, a0, bias[lane]), 0.f);
    float h1 = fmaxf(fmaf(d, a1, bias[lane + 32]), 0.f);

    if (!FUSE_FC) {
        g_h[warp * HID + lane]      = h0;
        g_h[warp * HID + 32 + lane] = h1;
    } else {
        float myout = 0.f;
#pragma unroll
        for (int o = 0; o < 10; o++) {
            float v = h0 * wfc_s[lane * 10 + o] + h1 * wfc_s[(lane + 32) * 10 + o];
#pragma unroll
            for (int off = 16; off; off >>= 1) v += __shfl_xor_sync(0xffffffffu, v, off);
            if (lane == o) myout = v;
        }
        if (lane < 10) OUT[warp * 10 + lane] = myout + bfc_s[lane];
    }
}

// ---------------- launch ----------------
extern "C" void kernel_launch(void* const* d_in, const int* in_sizes, int n_in,
                              void* d_out, int out_size) {
    const float* x   = (const float*)d_in[0];
    const void*  ei  = d_in[1];
    const float* W1  = (const float*)d_in[2];
    const float* b1  = (const float*)d_in[3];
    const float* W2  = (const float*)d_in[4];
    const float* b2  = (const float*)d_in[5];
    const float* Wfc = (const float*)d_in[6];
    const float* bfc = (const float*)d_in[7];
    float*       out = (float*)d_out;

    k_detect <<<1, 1>>>((const int*)ei);
    k_init   <<<(N_NODES + 255) / 256, 256>>>();
    k_hist   <<<(N_EDGES + 255) / 256, 256>>>(ei);
    k_scan   <<<1, 1024>>>();
    k_scatter<<<(N_EDGES + 255) / 256, 256>>>(ei);

    int tgrid = (N_NODES + 63) / 64;
    int agrid = (N_NODES * 32 + 255) / 256;

    k_transform<false><<<tgrid, 256>>>(x, W1);
    k_agg<false>      <<<agrid, 256>>>(b1, nullptr, nullptr, nullptr);
    k_transform<true> <<<tgrid, 256>>>(nullptr, W2);
    k_agg<true>       <<<agrid, 256>>>(b2, Wfc, bfc, out);
}

// round 3
// speedup vs baseline: 1.8403x; 1.8403x over previous
#include <cuda_runtime.h>

#define N_NODES 50000
#define N_EDGES 1600000
#define E_TOT   (N_EDGES + N_NODES)
#define HID 64
#define SCAN_BLK 256
#define N_SBLKS ((N_NODES + SCAN_BLK - 1) / SCAN_BLK)   // 196

// ---------------- scratch (static __device__: no allocation allowed) ----------------
__device__ int   g_is64;                // 1 if edge_index is int64, 0 if int32
__device__ int   g_deg[N_NODES];
__device__ float g_dis[N_NODES];
__device__ int   g_offs[N_NODES + 1];
__device__ int   g_cursor[N_NODES];
__device__ int   g_csr[E_TOT];
__device__ int   g_blkoff[N_SBLKS];     // scanned block offsets
__device__ float g_ts[N_NODES * HID];   // dis-scaled transformed features (both layers)
__device__ float g_h [N_NODES * HID];   // layer-1 hidden output

// Dtype-dispatching edge-index load. ei is the base of edge_index [2, N_EDGES].
__device__ __forceinline__ int load_ei(const void* ei, long long flat_idx, int is64) {
    if (is64) return (int)((const long long*)ei)[flat_idx];
    return ((const int*)ei)[flat_idx];
}

// ---------------- dtype detection ----------------
// If int64: high word of each entry is 0 (indices in [0, 50000)). If int32:
// "high words" are other random indices; 64 of them all zero is impossible.
__global__ void k_detect(const int* __restrict__ ei_words) {
    int allzero = 1;
    for (int k = 0; k < 64; k++)
        if (ei_words[2 * k + 1] != 0) { allzero = 0; break; }
    g_is64 = allzero;
}

// ---------------- CSR build ----------------
__global__ void k_init() {
    int i = blockIdx.x * blockDim.x + threadIdx.x;
    if (i < N_NODES) g_deg[i] = 1;            // self-loop
}

__global__ void k_hist(const void* __restrict__ ei) {
    int e = blockIdx.x * blockDim.x + threadIdx.x;
    if (e < N_EDGES) {
        int d = load_ei(ei, (long long)N_EDGES + e, g_is64);
        atomicAdd(&g_deg[d], 1);
    }
}

// ---- phase 1: per-block degree sums -> g_blkoff (unscanned) ----
__global__ void __launch_bounds__(SCAN_BLK) k_scan1() {
    __shared__ int wsum[SCAN_BLK / 32];
    int i = blockIdx.x * SCAN_BLK + threadIdx.x;
    int v = (i < N_NODES) ? g_deg[i] : 0;
#pragma unroll
    for (int off = 16; off; off >>= 1) v += __shfl_xor_sync(0xffffffffu, v, off);
    int lane = threadIdx.x & 31, wid = threadIdx.x >> 5;
    if (lane == 0) wsum[wid] = v;
    __syncthreads();
    if (threadIdx.x == 0) {
        int s = 0;
#pragma unroll
        for (int w = 0; w < SCAN_BLK / 32; w++) s += wsum[w];
        g_blkoff[blockIdx.x] = s;
    }
}

// ---- phase 2: exclusive scan of 196 block sums (single tiny block) ----
__global__ void __launch_bounds__(256) k_scan2() {
    __shared__ int s[256];
    int t = threadIdx.x;
    int v = (t < N_SBLKS) ? g_blkoff[t] : 0;
    s[t] = v;
    __syncthreads();
#pragma unroll
    for (int off = 1; off < 256; off <<= 1) {
        int u = (t >= off) ? s[t - off] : 0;
        __syncthreads();
        s[t] += u;
        __syncthreads();
    }
    if (t < N_SBLKS) g_blkoff[t] = s[t] - v;      // exclusive
    if (t == 0) g_offs[N_NODES] = E_TOT;          // total is a constant
}

// ---- phase 3: intra-block exclusive scan + emit offs/dis/cursor/self-loop ----
__global__ void __launch_bounds__(SCAN_BLK) k_scan3() {
    __shared__ int wsum[SCAN_BLK / 32];
    int i = blockIdx.x * SCAN_BLK + threadIdx.x;
    int d = (i < N_NODES) ? g_deg[i] : 0;
    int lane = threadIdx.x & 31, wid = threadIdx.x >> 5;
    int v = d;
#pragma unroll
    for (int off = 1; off < 32; off <<= 1) {
        int n = __shfl_up_sync(0xffffffffu, v, off);
        if (lane >= off) v += n;
    }
    if (lane == 31) wsum[wid] = v;
    __syncthreads();
    if (wid == 0) {
        int w = (lane < SCAN_BLK / 32) ? wsum[lane] : 0;
#pragma unroll
        for (int off = 1; off < SCAN_BLK / 32; off <<= 1) {
            int n = __shfl_up_sync(0xffffffffu, w, off);
            if (lane >= off) w += n;
        }
        if (lane < SCAN_BLK / 32) wsum[lane] = w;
    }
    __syncthreads();
    int excl = v - d + (wid ? wsum[wid - 1] : 0) + g_blkoff[blockIdx.x];
    if (i < N_NODES) {
        g_offs[i]   = excl;
        g_dis[i]    = rsqrtf((float)d);           // deg >= 1 always (self-loop)
        g_cursor[i] = excl + 1;
        g_csr[excl] = i;                          // self-loop entry first
    }
}

__global__ void k_scatter(const void* __restrict__ ei) {
    int e = blockIdx.x * blockDim.x + threadIdx.x;
    if (e < N_EDGES) {
        int is64 = g_is64;
        int d = load_ei(ei, (long long)N_EDGES + e, is64);
        int s = load_ei(ei, e, is64);
        int pos = atomicAdd(&g_cursor[d], 1);
        g_csr[pos] = s;
    }
}

// ---------------- transform: OUT[i] = dis[i] * (X[i] @ W)  (64x64 weight) ----------------
// Block: 256 threads = 16x16, 4x4 register blocking on a 64-row x 64-col tile.
template <bool USE_H>
__global__ void __launch_bounds__(256) k_transform(const float* __restrict__ Xext,
                                                   const float* __restrict__ W) {
    __shared__ float4 ws4[64 * 16];
    __shared__ float  xs [64 * 64];
    const float* X = USE_H ? g_h : Xext;
    int tid  = threadIdx.x;
    int row0 = blockIdx.x * 64;

    for (int i = tid; i < 64 * 16; i += 256) ws4[i] = ((const float4*)W)[i];
    for (int i = tid; i < 64 * 16; i += 256) {
        int r = i >> 4, c4 = i & 15;
        int row = row0 + r;
        float4 v = make_float4(0.f, 0.f, 0.f, 0.f);
        if (row < N_NODES) v = ((const float4*)X)[row * 16 + c4];
        ((float4*)xs)[r * 16 + c4] = v;
    }
    __syncthreads();

    int tc = tid & 15, tr = tid >> 4;
    float acc[4][4];
#pragma unroll
    for (int a = 0; a < 4; a++)
#pragma unroll
        for (int b = 0; b < 4; b++) acc[a][b] = 0.f;

#pragma unroll 4
    for (int k = 0; k < 64; k++) {
        float4 wv = ws4[k * 16 + tc];
        float x0 = xs[(4 * tr + 0) * 64 + k];
        float x1 = xs[(4 * tr + 1) * 64 + k];
        float x2 = xs[(4 * tr + 2) * 64 + k];
        float x3 = xs[(4 * tr + 3) * 64 + k];
        acc[0][0] = fmaf(x0, wv.x, acc[0][0]); acc[0][1] = fmaf(x0, wv.y, acc[0][1]);
        acc[0][2] = fmaf(x0, wv.z, acc[0][2]); acc[0][3] = fmaf(x0, wv.w, acc[0][3]);
        acc[1][0] = fmaf(x1, wv.x, acc[1][0]); acc[1][1] = fmaf(x1, wv.y, acc[1][1]);
        acc[1][2] = fmaf(x1, wv.z, acc[1][2]); acc[1][3] = fmaf(x1, wv.w, acc[1][3]);
        acc[2][0] = fmaf(x2, wv.x, acc[2][0]); acc[2][1] = fmaf(x2, wv.y, acc[2][1]);
        acc[2][2] = fmaf(x2, wv.z, acc[2][2]); acc[2][3] = fmaf(x2, wv.w, acc[2][3]);
        acc[3][0] = fmaf(x3, wv.x, acc[3][0]); acc[3][1] = fmaf(x3, wv.y, acc[3][1]);
        acc[3][2] = fmaf(x3, wv.z, acc[3][2]); acc[3][3] = fmaf(x3, wv.w, acc[3][3]);
    }

#pragma unroll
    for (int jr = 0; jr < 4; jr++) {
        int row = row0 + 4 * tr + jr;
        if (row < N_NODES) {
            float sc = g_dis[row];
            float4 o = make_float4(acc[jr][0] * sc, acc[jr][1] * sc,
                                   acc[jr][2] * sc, acc[jr][3] * sc);
            ((float4*)g_ts)[row * 16 + tc] = o;
        }
    }
}

// ---------------- aggregate: one warp per node, CSR gather-sum, no atomics ----------------
// h[d] = relu(dis[d] * sum_{s in N(d)} ts[s] + b)
// FUSE_FC: instead of storing h, compute out = h @ Wfc + bfc (64 -> 10) via warp reduction.
template <bool FUSE_FC>
__global__ void __launch_bounds__(256) k_agg(const float* __restrict__ bias,
                                             const float* __restrict__ WFC,
                                             const float* __restrict__ BFC,
                                             float* __restrict__ OUT) {
    __shared__ float wfc_s[64 * 10];
    __shared__ float bfc_s[10];
    if (FUSE_FC) {
        for (int i = threadIdx.x; i < 640; i += blockDim.x) wfc_s[i] = WFC[i];
        if (threadIdx.x < 10) bfc_s[threadIdx.x] = BFC[threadIdx.x];
        __syncthreads();
    }
    int warp = (blockIdx.x * blockDim.x + threadIdx.x) >> 5;
    int lane = threadIdx.x & 31;
    if (warp >= N_NODES) return;

    int beg = g_offs[warp], end = g_offs[warp + 1];
    float a0 = 0.f, a1 = 0.f;
    int j = beg;
    for (; j + 4 <= end; j += 4) {
        int s0 = g_csr[j + 0], s1 = g_csr[j + 1];
        int s2 = g_csr[j + 2], s3 = g_csr[j + 3];
        const float* p0 = g_ts + s0 * HID;
        const float* p1 = g_ts + s1 * HID;
        const float* p2 = g_ts + s2 * HID;
        const float* p3 = g_ts + s3 * HID;
        float v00 = p0[lane], v01 = p0[lane + 32];
        float v10 = p1[lane], v11 = p1[lane + 32];
        float v20 = p2[lane], v21 = p2[lane + 32];
        float v30 = p3[lane], v31 = p3[lane + 32];
        a0 += (v00 + v10) + (v20 + v30);
        a1 += (v01 + v11) + (v21 + v31);
    }
    for (; j < end; j++) {
        int s0 = g_csr[j];
        a0 += g_ts[s0 * HID + lane];
        a1 += g_ts[s0 * HID + 32 + lane];
    }
    float d  = g_dis[warp];
    float h0 = fmaxf(fmaf(d, a0, bias[lane]), 0.f);
    float h1 = fmaxf(fmaf(d, a1, bias[lane + 32]), 0.f);

    if (!FUSE_FC) {
        g_h[warp * HID + lane]      = h0;
        g_h[warp * HID + 32 + lane] = h1;
    } else {
        float myout = 0.f;
#pragma unroll
        for (int o = 0; o < 10; o++) {
            float v = h0 * wfc_s[lane * 10 + o] + h1 * wfc_s[(lane + 32) * 10 + o];
#pragma unroll
            for (int off = 16; off; off >>= 1) v += __shfl_xor_sync(0xffffffffu, v, off);
            if (lane == o) myout = v;
        }
        if (lane < 10) OUT[warp * 10 + lane] = myout + bfc_s[lane];
    }
}

// ---------------- launch ----------------
extern "C" void kernel_launch(void* const* d_in, const int* in_sizes, int n_in,
                              void* d_out, int out_size) {
    const float* x   = (const float*)d_in[0];
    const void*  ei  = d_in[1];
    const float* W1  = (const float*)d_in[2];
    const float* b1  = (const float*)d_in[3];
    const float* W2  = (const float*)d_in[4];
    const float* b2  = (const float*)d_in[5];
    const float* Wfc = (const float*)d_in[6];
    const float* bfc = (const float*)d_in[7];
    float*       out = (float*)d_out;

    k_detect <<<1, 1>>>((const int*)ei);
    k_init   <<<(N_NODES + 255) / 256, 256>>>();
    k_hist   <<<(N_EDGES + 255) / 256, 256>>>(ei);
    k_scan1  <<<N_SBLKS, SCAN_BLK>>>();
    k_scan2  <<<1, 256>>>();
    k_scan3  <<<N_SBLKS, SCAN_BLK>>>();
    k_scatter<<<(N_EDGES + 255) / 256, 256>>>(ei);

    int tgrid = (N_NODES + 63) / 64;
    int agrid = (N_NODES * 32 + 255) / 256;

    k_transform<false><<<tgrid, 256>>>(x, W1);
    k_agg<false>      <<<agrid, 256>>>(b1, nullptr, nullptr, nullptr);
    k_transform<true> <<<tgrid, 256>>>(nullptr, W2);
    k_agg<true>       <<<agrid, 256>>>(b2, Wfc, bfc, out);
}

// round 4
// speedup vs baseline: 1.9282x; 1.0478x over previous
#include <cuda_runtime.h>

#define N_NODES 50000
#define N_EDGES 1600000
#define E_TOT   (N_EDGES + N_NODES)
#define HID 64
#define SCAN_BLK 256
#define N_SBLKS ((N_NODES + SCAN_BLK - 1) / SCAN_BLK)   // 196

// ---------------- scratch (static __device__: no allocation allowed) ----------------
__device__ int   g_is64;                // 1 if edge_index is int64, 0 if int32
__device__ int   g_deg[N_NODES];
__device__ float g_dis[N_NODES];
__device__ int   g_offs[N_NODES + 1];
__device__ int   g_cursor[N_NODES];
__device__ int   g_csr[E_TOT];
__device__ int   g_blkoff[N_SBLKS];     // scanned block offsets
__device__ float g_ts[N_NODES * HID];   // dis-scaled transformed features (both layers)
__device__ float g_h [N_NODES * HID];   // layer-1 hidden output

// Dtype-dispatching edge-index load. ei is the base of edge_index [2, N_EDGES].
__device__ __forceinline__ int load_ei(const void* ei, long long flat_idx, int is64) {
    if (is64) return (int)((const long long*)ei)[flat_idx];
    return ((const int*)ei)[flat_idx];
}

// ---------------- init + dtype detection (fused) ----------------
// If int64: high word of each entry is 0 (indices in [0, 50000)). If int32:
// "high words" are other random indices; 64 of them all zero is impossible.
__global__ void k_init(const int* __restrict__ ei_words) {
    int i = blockIdx.x * blockDim.x + threadIdx.x;
    if (i < N_NODES) g_deg[i] = 1;            // self-loop
    if (i == 0) {
        int allzero = 1;
        for (int k = 0; k < 64; k++)
            if (ei_words[2 * k + 1] != 0) { allzero = 0; break; }
        g_is64 = allzero;
    }
}

__global__ void k_hist(const void* __restrict__ ei) {
    int e = blockIdx.x * blockDim.x + threadIdx.x;
    if (e < N_EDGES) {
        int d = load_ei(ei, (long long)N_EDGES + e, g_is64);
        atomicAdd(&g_deg[d], 1);
    }
}

// ---- phase 1: per-block degree sums -> g_blkoff (unscanned) ----
__global__ void __launch_bounds__(SCAN_BLK) k_scan1() {
    __shared__ int wsum[SCAN_BLK / 32];
    int i = blockIdx.x * SCAN_BLK + threadIdx.x;
    int v = (i < N_NODES) ? g_deg[i] : 0;
#pragma unroll
    for (int off = 16; off; off >>= 1) v += __shfl_xor_sync(0xffffffffu, v, off);
    int lane = threadIdx.x & 31, wid = threadIdx.x >> 5;
    if (lane == 0) wsum[wid] = v;
    __syncthreads();
    if (threadIdx.x == 0) {
        int s = 0;
#pragma unroll
        for (int w = 0; w < SCAN_BLK / 32; w++) s += wsum[w];
        g_blkoff[blockIdx.x] = s;
    }
}

// ---- phase 2: exclusive scan of 196 block sums (single tiny block) ----
__global__ void __launch_bounds__(256) k_scan2() {
    __shared__ int s[256];
    int t = threadIdx.x;
    int v = (t < N_SBLKS) ? g_blkoff[t] : 0;
    s[t] = v;
    __syncthreads();
#pragma unroll
    for (int off = 1; off < 256; off <<= 1) {
        int u = (t >= off) ? s[t - off] : 0;
        __syncthreads();
        s[t] += u;
        __syncthreads();
    }
    if (t < N_SBLKS) g_blkoff[t] = s[t] - v;      // exclusive
    if (t == 0) g_offs[N_NODES] = E_TOT;          // total is a constant
}

// ---- phase 3: intra-block exclusive scan + emit offs/dis/cursor/self-loop ----
__global__ void __launch_bounds__(SCAN_BLK) k_scan3() {
    __shared__ int wsum[SCAN_BLK / 32];
    int i = blockIdx.x * SCAN_BLK + threadIdx.x;
    int d = (i < N_NODES) ? g_deg[i] : 0;
    int lane = threadIdx.x & 31, wid = threadIdx.x >> 5;
    int v = d;
#pragma unroll
    for (int off = 1; off < 32; off <<= 1) {
        int n = __shfl_up_sync(0xffffffffu, v, off);
        if (lane >= off) v += n;
    }
    if (lane == 31) wsum[wid] = v;
    __syncthreads();
    if (wid == 0) {
        int w = (lane < SCAN_BLK / 32) ? wsum[lane] : 0;
#pragma unroll
        for (int off = 1; off < SCAN_BLK / 32; off <<= 1) {
            int n = __shfl_up_sync(0xffffffffu, w, off);
            if (lane >= off) w += n;
        }
        if (lane < SCAN_BLK / 32) wsum[lane] = w;
    }
    __syncthreads();
    int excl = v - d + (wid ? wsum[wid - 1] : 0) + g_blkoff[blockIdx.x];
    if (i < N_NODES) {
        g_offs[i]   = excl;
        g_dis[i]    = rsqrtf((float)d);           // deg >= 1 always (self-loop)
        g_cursor[i] = excl + 1;
        g_csr[excl] = i;                          // self-loop entry first
    }
}

__global__ void k_scatter(const void* __restrict__ ei) {
    int e = blockIdx.x * blockDim.x + threadIdx.x;
    if (e < N_EDGES) {
        int is64 = g_is64;
        int d = load_ei(ei, (long long)N_EDGES + e, is64);
        int s = load_ei(ei, e, is64);
        int pos = atomicAdd(&g_cursor[d], 1);
        g_csr[pos] = s;
    }
}

// ---------------- transform: OUT[i] = dis[i] * (X[i] @ W)  (64x64 weight) ----------------
// Block: 256 threads = 16x16, 4x4 register blocking on a 64-row x 64-col tile.
template <bool USE_H>
__global__ void __launch_bounds__(256) k_transform(const float* __restrict__ Xext,
                                                   const float* __restrict__ W) {
    __shared__ float4 ws4[64 * 16];
    __shared__ float  xs [64 * 64];
    const float* X = USE_H ? g_h : Xext;
    int tid  = threadIdx.x;
    int row0 = blockIdx.x * 64;

    for (int i = tid; i < 64 * 16; i += 256) ws4[i] = ((const float4*)W)[i];
    for (int i = tid; i < 64 * 16; i += 256) {
        int r = i >> 4, c4 = i & 15;
        int row = row0 + r;
        float4 v = make_float4(0.f, 0.f, 0.f, 0.f);
        if (row < N_NODES) v = ((const float4*)X)[row * 16 + c4];
        ((float4*)xs)[r * 16 + c4] = v;
    }
    __syncthreads();

    int tc = tid & 15, tr = tid >> 4;
    float acc[4][4];
#pragma unroll
    for (int a = 0; a < 4; a++)
#pragma unroll
        for (int b = 0; b < 4; b++) acc[a][b] = 0.f;

#pragma unroll 4
    for (int k = 0; k < 64; k++) {
        float4 wv = ws4[k * 16 + tc];
        float x0 = xs[(4 * tr + 0) * 64 + k];
        float x1 = xs[(4 * tr + 1) * 64 + k];
        float x2 = xs[(4 * tr + 2) * 64 + k];
        float x3 = xs[(4 * tr + 3) * 64 + k];
        acc[0][0] = fmaf(x0, wv.x, acc[0][0]); acc[0][1] = fmaf(x0, wv.y, acc[0][1]);
        acc[0][2] = fmaf(x0, wv.z, acc[0][2]); acc[0][3] = fmaf(x0, wv.w, acc[0][3]);
        acc[1][0] = fmaf(x1, wv.x, acc[1][0]); acc[1][1] = fmaf(x1, wv.y, acc[1][1]);
        acc[1][2] = fmaf(x1, wv.z, acc[1][2]); acc[1][3] = fmaf(x1, wv.w, acc[1][3]);
        acc[2][0] = fmaf(x2, wv.x, acc[2][0]); acc[2][1] = fmaf(x2, wv.y, acc[2][1]);
        acc[2][2] = fmaf(x2, wv.z, acc[2][2]); acc[2][3] = fmaf(x2, wv.w, acc[2][3]);
        acc[3][0] = fmaf(x3, wv.x, acc[3][0]); acc[3][1] = fmaf(x3, wv.y, acc[3][1]);
        acc[3][2] = fmaf(x3, wv.z, acc[3][2]); acc[3][3] = fmaf(x3, wv.w, acc[3][3]);
    }

#pragma unroll
    for (int jr = 0; jr < 4; jr++) {
        int row = row0 + 4 * tr + jr;
        if (row < N_NODES) {
            float sc = g_dis[row];
            float4 o = make_float4(acc[jr][0] * sc, acc[jr][1] * sc,
                                   acc[jr][2] * sc, acc[jr][3] * sc);
            ((float4*)g_ts)[row * 16 + tc] = o;
        }
    }
}

// ---------------- aggregate: one warp per node, CSR gather-sum, no atomics ----------------
// Each lane owns feature pair (2*lane, 2*lane+1); one LDG.64 covers a full 256B row.
// h[d] = relu(dis[d] * sum_{s in N(d)} ts[s] + b)
// FUSE_FC: instead of storing h, compute out = h @ Wfc + bfc (64 -> 10) via warp reduction.
template <bool FUSE_FC>
__global__ void __launch_bounds__(256) k_agg(const float* __restrict__ bias,
                                             const float* __restrict__ WFC,
                                             const float* __restrict__ BFC,
                                             float* __restrict__ OUT) {
    __shared__ float wfc_s[64 * 10];
    __shared__ float bfc_s[10];
    if (FUSE_FC) {
        for (int i = threadIdx.x; i < 640; i += blockDim.x) wfc_s[i] = WFC[i];
        if (threadIdx.x < 10) bfc_s[threadIdx.x] = BFC[threadIdx.x];
        __syncthreads();
    }
    int warp = (blockIdx.x * blockDim.x + threadIdx.x) >> 5;
    int lane = threadIdx.x & 31;
    if (warp >= N_NODES) return;

    int beg = g_offs[warp], end = g_offs[warp + 1];
    float ax = 0.f, ay = 0.f;
    const float2* ts2 = (const float2*)g_ts;   // row r at ts2[r*32 + lane]
    int j = beg;
    // 8 independent LDG.64 in flight per iteration
    for (; j + 8 <= end; j += 8) {
        int s0 = g_csr[j + 0], s1 = g_csr[j + 1], s2 = g_csr[j + 2], s3 = g_csr[j + 3];
        int s4 = g_csr[j + 4], s5 = g_csr[j + 5], s6 = g_csr[j + 6], s7 = g_csr[j + 7];
        float2 v0 = ts2[s0 * 32 + lane];
        float2 v1 = ts2[s1 * 32 + lane];
        float2 v2 = ts2[s2 * 32 + lane];
        float2 v3 = ts2[s3 * 32 + lane];
        float2 v4 = ts2[s4 * 32 + lane];
        float2 v5 = ts2[s5 * 32 + lane];
        float2 v6 = ts2[s6 * 32 + lane];
        float2 v7 = ts2[s7 * 32 + lane];
        ax += ((v0.x + v1.x) + (v2.x + v3.x)) + ((v4.x + v5.x) + (v6.x + v7.x));
        ay += ((v0.y + v1.y) + (v2.y + v3.y)) + ((v4.y + v5.y) + (v6.y + v7.y));
    }
    for (; j + 2 <= end; j += 2) {
        int s0 = g_csr[j + 0], s1 = g_csr[j + 1];
        float2 v0 = ts2[s0 * 32 + lane];
        float2 v1 = ts2[s1 * 32 + lane];
        ax += v0.x + v1.x;
        ay += v0.y + v1.y;
    }
    if (j < end) {
        float2 v0 = ts2[g_csr[j] * 32 + lane];
        ax += v0.x;
        ay += v0.y;
    }
    float d  = g_dis[warp];
    float2 b2 = ((const float2*)bias)[lane];
    float h0 = fmaxf(fmaf(d, ax, b2.x), 0.f);
    float h1 = fmaxf(fmaf(d, ay, b2.y), 0.f);

    if (!FUSE_FC) {
        ((float2*)g_h)[warp * 32 + lane] = make_float2(h0, h1);
    } else {
        float myout = 0.f;
#pragma unroll
        for (int o = 0; o < 10; o++) {
            float v = h0 * wfc_s[(2 * lane) * 10 + o] + h1 * wfc_s[(2 * lane + 1) * 10 + o];
#pragma unroll
            for (int off = 16; off; off >>= 1) v += __shfl_xor_sync(0xffffffffu, v, off);
            if (lane == o) myout = v;
        }
        if (lane < 10) OUT[warp * 10 + lane] = myout + bfc_s[lane];
    }
}

// ---------------- launch ----------------
extern "C" void kernel_launch(void* const* d_in, const int* in_sizes, int n_in,
                              void* d_out, int out_size) {
    const float* x   = (const float*)d_in[0];
    const void*  ei  = d_in[1];
    const float* W1  = (const float*)d_in[2];
    const float* b1  = (const float*)d_in[3];
    const float* W2  = (const float*)d_in[4];
    const float* b2  = (const float*)d_in[5];
    const float* Wfc = (const float*)d_in[6];
    const float* bfc = (const float*)d_in[7];
    float*       out = (float*)d_out;

    k_init   <<<(N_NODES + 255) / 256, 256>>>((const int*)ei);
    k_hist   <<<(N_EDGES + 255) / 256, 256>>>(ei);
    k_scan1  <<<N_SBLKS, SCAN_BLK>>>();
    k_scan2  <<<1, 256>>>();
    k_scan3  <<<N_SBLKS, SCAN_BLK>>>();
    k_scatter<<<(N_EDGES + 255) / 256, 256>>>(ei);

    int tgrid = (N_NODES + 63) / 64;
    int agrid = (N_NODES * 32 + 255) / 256;

    k_transform<false><<<tgrid, 256>>>(x, W1);
    k_agg<false>      <<<agrid, 256>>>(b1, nullptr, nullptr, nullptr);
    k_transform<true> <<<tgrid, 256>>>(nullptr, W2);
    k_agg<true>       <<<agrid, 256>>>(b2, Wfc, bfc, out);
}

// round 5
// speedup vs baseline: 2.0117x; 1.0433x over previous
#include <cuda_runtime.h>
#include <cuda_fp16.h>

#define N_NODES 50000
#define N_EDGES 1600000
#define E_TOT   (N_EDGES + N_NODES)
#define HID 64
#define SCAN_BLK 256
#define N_SBLKS ((N_NODES + SCAN_BLK - 1) / SCAN_BLK)   // 196

// ---------------- scratch (static __device__: no allocation allowed) ----------------
__device__ int     g_is64;                // 1 if edge_index is int64, 0 if int32
__device__ int     g_deg[N_NODES];
__device__ float   g_dis[N_NODES];
__device__ int     g_offs[N_NODES + 1];
__device__ int     g_cursor[N_NODES];
__device__ int     g_csr[E_TOT];
__device__ int     g_blkoff[N_SBLKS];     // scanned block offsets
__device__ __half2 g_ts[N_NODES * 32];    // dis-scaled transformed features (fp16, both layers)
__device__ float   g_h [N_NODES * HID];   // layer-1 hidden output (fp32)

// ---------------- init + dtype detection (fused) ----------------
// If int64: high word of each entry is 0 (indices in [0, 50000)). If int32:
// "high words" are other random indices; 64 of them all zero is impossible.
__global__ void k_init(const int* __restrict__ ei_words) {
    int i = blockIdx.x * blockDim.x + threadIdx.x;
    if (i < N_NODES) g_deg[i] = 1;            // self-loop
    if (i == 0) {
        int allzero = 1;
        for (int k = 0; k < 64; k++)
            if (ei_words[2 * k + 1] != 0) { allzero = 0; break; }
        g_is64 = allzero;
    }
}

// ---------------- CSR build: 4 edges per thread, vectorized index loads ----------------
// N_EDGES % 4 == 0, so no tail handling.
__global__ void k_hist(const void* __restrict__ ei) {
    int t = blockIdx.x * blockDim.x + threadIdx.x;
    if (t >= N_EDGES / 4) return;
    int d0, d1, d2, d3;
    if (g_is64) {
        const int4* p = (const int4*)((const long long*)ei + N_EDGES);  // dst base
        int4 a = p[2 * t], b = p[2 * t + 1];
        d0 = a.x; d1 = a.z; d2 = b.x; d3 = b.z;
    } else {
        const int4* p = (const int4*)((const int*)ei + N_EDGES);
        int4 a = p[t];
        d0 = a.x; d1 = a.y; d2 = a.z; d3 = a.w;
    }
    atomicAdd(&g_deg[d0], 1);
    atomicAdd(&g_deg[d1], 1);
    atomicAdd(&g_deg[d2], 1);
    atomicAdd(&g_deg[d3], 1);
}

// ---- phase 1: per-block degree sums -> g_blkoff (unscanned) ----
__global__ void __launch_bounds__(SCAN_BLK) k_scan1() {
    __shared__ int wsum[SCAN_BLK / 32];
    int i = blockIdx.x * SCAN_BLK + threadIdx.x;
    int v = (i < N_NODES) ? g_deg[i] : 0;
#pragma unroll
    for (int off = 16; off; off >>= 1) v += __shfl_xor_sync(0xffffffffu, v, off);
    int lane = threadIdx.x & 31, wid = threadIdx.x >> 5;
    if (lane == 0) wsum[wid] = v;
    __syncthreads();
    if (threadIdx.x == 0) {
        int s = 0;
#pragma unroll
        for (int w = 0; w < SCAN_BLK / 32; w++) s += wsum[w];
        g_blkoff[blockIdx.x] = s;
    }
}

// ---- phase 2: exclusive scan of 196 block sums (single tiny block) ----
__global__ void __launch_bounds__(256) k_scan2() {
    __shared__ int s[256];
    int t = threadIdx.x;
    int v = (t < N_SBLKS) ? g_blkoff[t] : 0;
    s[t] = v;
    __syncthreads();
#pragma unroll
    for (int off = 1; off < 256; off <<= 1) {
        int u = (t >= off) ? s[t - off] : 0;
        __syncthreads();
        s[t] += u;
        __syncthreads();
    }
    if (t < N_SBLKS) g_blkoff[t] = s[t] - v;      // exclusive
    if (t == 0) g_offs[N_NODES] = E_TOT;          // total is a constant
}

// ---- phase 3: intra-block exclusive scan + emit offs/dis/cursor/self-loop ----
__global__ void __launch_bounds__(SCAN_BLK) k_scan3() {
    __shared__ int wsum[SCAN_BLK / 32];
    int i = blockIdx.x * SCAN_BLK + threadIdx.x;
    int d = (i < N_NODES) ? g_deg[i] : 0;
    int lane = threadIdx.x & 31, wid = threadIdx.x >> 5;
    int v = d;
#pragma unroll
    for (int off = 1; off < 32; off <<= 1) {
        int n = __shfl_up_sync(0xffffffffu, v, off);
        if (lane >= off) v += n;
    }
    if (lane == 31) wsum[wid] = v;
    __syncthreads();
    if (wid == 0) {
        int w = (lane < SCAN_BLK / 32) ? wsum[lane] : 0;
#pragma unroll
        for (int off = 1; off < SCAN_BLK / 32; off <<= 1) {
            int n = __shfl_up_sync(0xffffffffu, w, off);
            if (lane >= off) w += n;
        }
        if (lane < SCAN_BLK / 32) wsum[lane] = w;
    }
    __syncthreads();
    int excl = v - d + (wid ? wsum[wid - 1] : 0) + g_blkoff[blockIdx.x];
    if (i < N_NODES) {
        g_offs[i]   = excl;
        g_dis[i]    = rsqrtf((float)d);           // deg >= 1 always (self-loop)
        g_cursor[i] = excl + 1;
        g_csr[excl] = i;                          // self-loop entry first
    }
}

__global__ void k_scatter(const void* __restrict__ ei) {
    int t = blockIdx.x * blockDim.x + threadIdx.x;
    if (t >= N_EDGES / 4) return;
    int d0, d1, d2, d3, s0, s1, s2, s3;
    if (g_is64) {
        const int4* pd = (const int4*)((const long long*)ei + N_EDGES);
        const int4* ps = (const int4*)((const long long*)ei);
        int4 a = pd[2 * t], b = pd[2 * t + 1];
        int4 c = ps[2 * t], e = ps[2 * t + 1];
        d0 = a.x; d1 = a.z; d2 = b.x; d3 = b.z;
        s0 = c.x; s1 = c.z; s2 = e.x; s3 = e.z;
    } else {
        const int4* pd = (const int4*)((const int*)ei + N_EDGES);
        const int4* ps = (const int4*)((const int*)ei);
        int4 a = pd[t], c = ps[t];
        d0 = a.x; d1 = a.y; d2 = a.z; d3 = a.w;
        s0 = c.x; s1 = c.y; s2 = c.z; s3 = c.w;
    }
    g_csr[atomicAdd(&g_cursor[d0], 1)] = s0;
    g_csr[atomicAdd(&g_cursor[d1], 1)] = s1;
    g_csr[atomicAdd(&g_cursor[d2], 1)] = s2;
    g_csr[atomicAdd(&g_cursor[d3], 1)] = s3;
}

// ---------------- transform: TS[i] = fp16( dis[i] * (X[i] @ W) )  (64x64 weight) ----------------
// Block: 256 threads = 16x16, 4x4 register blocking on a 64-row x 64-col tile.
template <bool USE_H>
__global__ void __launch_bounds__(256) k_transform(const float* __restrict__ Xext,
                                                   const float* __restrict__ W) {
    __shared__ float4 ws4[64 * 16];
    __shared__ float  xs [64 * 64];
    const float* X = USE_H ? g_h : Xext;
    int tid  = threadIdx.x;
    int row0 = blockIdx.x * 64;

    for (int i = tid; i < 64 * 16; i += 256) ws4[i] = ((const float4*)W)[i];
    for (int i = tid; i < 64 * 16; i += 256) {
        int r = i >> 4, c4 = i & 15;
        int row = row0 + r;
        float4 v = make_float4(0.f, 0.f, 0.f, 0.f);
        if (row < N_NODES) v = ((const float4*)X)[row * 16 + c4];
        ((float4*)xs)[r * 16 + c4] = v;
    }
    __syncthreads();

    int tc = tid & 15, tr = tid >> 4;
    float acc[4][4];
#pragma unroll
    for (int a = 0; a < 4; a++)
#pragma unroll
        for (int b = 0; b < 4; b++) acc[a][b] = 0.f;

#pragma unroll 4
    for (int k = 0; k < 64; k++) {
        float4 wv = ws4[k * 16 + tc];
        float x0 = xs[(4 * tr + 0) * 64 + k];
        float x1 = xs[(4 * tr + 1) * 64 + k];
        float x2 = xs[(4 * tr + 2) * 64 + k];
        float x3 = xs[(4 * tr + 3) * 64 + k];
        acc[0][0] = fmaf(x0, wv.x, acc[0][0]); acc[0][1] = fmaf(x0, wv.y, acc[0][1]);
        acc[0][2] = fmaf(x0, wv.z, acc[0][2]); acc[0][3] = fmaf(x0, wv.w, acc[0][3]);
        acc[1][0] = fmaf(x1, wv.x, acc[1][0]); acc[1][1] = fmaf(x1, wv.y, acc[1][1]);
        acc[1][2] = fmaf(x1, wv.z, acc[1][2]); acc[1][3] = fmaf(x1, wv.w, acc[1][3]);
        acc[2][0] = fmaf(x2, wv.x, acc[2][0]); acc[2][1] = fmaf(x2, wv.y, acc[2][1]);
        acc[2][2] = fmaf(x2, wv.z, acc[2][2]); acc[2][3] = fmaf(x2, wv.w, acc[2][3]);
        acc[3][0] = fmaf(x3, wv.x, acc[3][0]); acc[3][1] = fmaf(x3, wv.y, acc[3][1]);
        acc[3][2] = fmaf(x3, wv.z, acc[3][2]); acc[3][3] = fmaf(x3, wv.w, acc[3][3]);
    }

#pragma unroll
    for (int jr = 0; jr < 4; jr++) {
        int row = row0 + 4 * tr + jr;
        if (row < N_NODES) {
            float sc = g_dis[row];
            __half2 p0 = __float22half2_rn(make_float2(acc[jr][0] * sc, acc[jr][1] * sc));
            __half2 p1 = __float22half2_rn(make_float2(acc[jr][2] * sc, acc[jr][3] * sc));
            uint2 packed = make_uint2(*(unsigned*)&p0, *(unsigned*)&p1);
            ((uint2*)g_ts)[row * 16 + tc] = packed;   // row = 16 uint2 = 128B
        }
    }
}

// ---------------- aggregate: one warp per node, CSR gather-sum, no atomics ----------------
// Each lane owns feature pair (2*lane, 2*lane+1) as one half2; one LDG.32 covers a 128B row.
// h[d] = relu(dis[d] * sum_{s in N(d)} ts[s] + b); accumulation in fp32.
// FUSE_FC: instead of storing h, compute out = h @ Wfc + bfc (64 -> 10) via warp reduction.
template <bool FUSE_FC>
__global__ void __launch_bounds__(256) k_agg(const float* __restrict__ bias,
                                             const float* __restrict__ WFC,
                                             const float* __restrict__ BFC,
                                             float* __restrict__ OUT) {
    __shared__ float wfc_s[64 * 10];
    __shared__ float bfc_s[10];
    if (FUSE_FC) {
        for (int i = threadIdx.x; i < 640; i += blockDim.x) wfc_s[i] = WFC[i];
        if (threadIdx.x < 10) bfc_s[threadIdx.x] = BFC[threadIdx.x];
        __syncthreads();
    }
    int warp = (blockIdx.x * blockDim.x + threadIdx.x) >> 5;
    int lane = threadIdx.x & 31;
    if (warp >= N_NODES) return;

    int beg = g_offs[warp], end = g_offs[warp + 1];
    float ax = 0.f, ay = 0.f;
    int j = beg;
    // 8 independent LDG.32 in flight per iteration
    for (; j + 8 <= end; j += 8) {
        int s0 = g_csr[j + 0], s1 = g_csr[j + 1], s2 = g_csr[j + 2], s3 = g_csr[j + 3];
        int s4 = g_csr[j + 4], s5 = g_csr[j + 5], s6 = g_csr[j + 6], s7 = g_csr[j + 7];
        float2 v0 = __half22float2(g_ts[s0 * 32 + lane]);
        float2 v1 = __half22float2(g_ts[s1 * 32 + lane]);
        float2 v2 = __half22float2(g_ts[s2 * 32 + lane]);
        float2 v3 = __half22float2(g_ts[s3 * 32 + lane]);
        float2 v4 = __half22float2(g_ts[s4 * 32 + lane]);
        float2 v5 = __half22float2(g_ts[s5 * 32 + lane]);
        float2 v6 = __half22float2(g_ts[s6 * 32 + lane]);
        float2 v7 = __half22float2(g_ts[s7 * 32 + lane]);
        ax += ((v0.x + v1.x) + (v2.x + v3.x)) + ((v4.x + v5.x) + (v6.x + v7.x));
        ay += ((v0.y + v1.y) + (v2.y + v3.y)) + ((v4.y + v5.y) + (v6.y + v7.y));
    }
    for (; j + 2 <= end; j += 2) {
        int s0 = g_csr[j + 0], s1 = g_csr[j + 1];
        float2 v0 = __half22float2(g_ts[s0 * 32 + lane]);
        float2 v1 = __half22float2(g_ts[s1 * 32 + lane]);
        ax += v0.x + v1.x;
        ay += v0.y + v1.y;
    }
    if (j < end) {
        float2 v0 = __half22float2(g_ts[g_csr[j] * 32 + lane]);
        ax += v0.x;
        ay += v0.y;
    }
    float d  = g_dis[warp];
    float2 b2 = ((const float2*)bias)[lane];
    float h0 = fmaxf(fmaf(d, ax, b2.x), 0.f);
    float h1 = fmaxf(fmaf(d, ay, b2.y), 0.f);

    if (!FUSE_FC) {
        ((float2*)g_h)[warp * 32 + lane] = make_float2(h0, h1);
    } else {
        float myout = 0.f;
#pragma unroll
        for (int o = 0; o < 10; o++) {
            float v = h0 * wfc_s[(2 * lane) * 10 + o] + h1 * wfc_s[(2 * lane + 1) * 10 + o];
#pragma unroll
            for (int off = 16; off; off >>= 1) v += __shfl_xor_sync(0xffffffffu, v, off);
            if (lane == o) myout = v;
        }
        if (lane < 10) OUT[warp * 10 + lane] = myout + bfc_s[lane];
    }
}

// ---------------- launch ----------------
extern "C" void kernel_launch(void* const* d_in, const int* in_sizes, int n_in,
                              void* d_out, int out_size) {
    const float* x   = (const float*)d_in[0];
    const void*  ei  = d_in[1];
    const float* W1  = (const float*)d_in[2];
    const float* b1  = (const float*)d_in[3];
    const float* W2  = (const float*)d_in[4];
    const float* b2  = (const float*)d_in[5];
    const float* Wfc = (const float*)d_in[6];
    const float* bfc = (const float*)d_in[7];
    float*       out = (float*)d_out;

    k_init   <<<(N_NODES + 255) / 256, 256>>>((const int*)ei);
    k_hist   <<<(N_EDGES / 4 + 255) / 256, 256>>>(ei);
    k_scan1  <<<N_SBLKS, SCAN_BLK>>>();
    k_scan2  <<<1, 256>>>();
    k_scan3  <<<N_SBLKS, SCAN_BLK>>>();
    k_scatter<<<(N_EDGES / 4 + 255) / 256, 256>>>(ei);

    int tgrid = (N_NODES + 63) / 64;
    int agrid = (N_NODES * 32 + 255) / 256;

    k_transform<false><<<tgrid, 256>>>(x, W1);
    k_agg<false>      <<<agrid, 256>>>(b1, nullptr, nullptr, nullptr);
    k_transform<true> <<<tgrid, 256>>>(nullptr, W2);
    k_agg<true>       <<<agrid, 256>>>(b2, Wfc, bfc, out);
}